// round 1
// baseline (speedup 1.0000x reference)
#include <cuda_runtime.h>
#include <math.h>

// ---------------------------------------------------------------------------
// Qwen2.5 Vision windowed attention block, fp32 baseline.
//   T=2304, HIDDEN=1280, 16 heads x 80, windows of 64 (block-diagonal mask).
//   Phase 1: qkv = x @ Wqkv + bqkv          (SGEMM 2304x3840x1280)
//   Phase 2: RoPE on q,k (in-place)
//   Phase 3: per-(window,head) attention    (576 blocks of 64x64x80)
//   Phase 4: out = attn @ Wo + bo           (SGEMM 2304x1280x1280)
// ---------------------------------------------------------------------------

#define TT    2304
#define HIDN  1280
#define NH    16
#define HD    80
#define WIN   64
#define NWIN  (TT / WIN)      // 36
#define NQKV  (3 * HIDN)      // 3840

// Scratch (allocation-free rule: __device__ globals)
__device__ float g_qkv[TT * NQKV];    // 35.4 MB
__device__ float g_attn[TT * HIDN];   // 11.8 MB

// ---------------------------------------------------------------------------
// SGEMM: C[M,N] = A[M,K] @ B[K,N] + bias[N]
// BM=BN=128, BK=8, 256 threads, 8x8 per thread. All dims divide evenly
// for both call sites (M=2304, N in {3840,1280}, K=1280) -> no bounds checks.
// ---------------------------------------------------------------------------
__global__ __launch_bounds__(256, 2)
void sgemm_bias_kernel(const float* __restrict__ A,
                       const float* __restrict__ B,
                       const float* __restrict__ bias,
                       float* __restrict__ C,
                       int M, int N, int K)
{
    const int BM = 128, BN = 128, BK = 8, TM = 8, TN = 8;
    __shared__ float As[BK][BM];
    __shared__ float Bs[BK][BN];

    const int tid = threadIdx.x;
    const int bm = blockIdx.y * BM;
    const int bn = blockIdx.x * BN;

    const int tx = tid % 16;   // 16 across N
    const int ty = tid / 16;   // 16 down  M

    float acc[TM][TN];
#pragma unroll
    for (int i = 0; i < TM; i++)
#pragma unroll
        for (int j = 0; j < TN; j++) acc[i][j] = 0.0f;

    // A tile load: 128x8 floats = 256 float4
    const int a_row = tid >> 1;         // 0..127
    const int a_col = (tid & 1) * 4;    // 0 or 4
    // B tile load: 8x128 floats = 256 float4
    const int b_row = tid >> 5;         // 0..7
    const int b_col = (tid & 31) * 4;   // 0..124

    const float* Ap = A + (size_t)(bm + a_row) * K + a_col;
    const float* Bp = B + (size_t)b_row * N + bn + b_col;

    for (int k0 = 0; k0 < K; k0 += BK) {
        float4 av = *(const float4*)(Ap + k0);
        As[a_col + 0][a_row] = av.x;
        As[a_col + 1][a_row] = av.y;
        As[a_col + 2][a_row] = av.z;
        As[a_col + 3][a_row] = av.w;
        float4 bv = *(const float4*)(Bp + (size_t)k0 * N);
        *(float4*)&Bs[b_row][b_col] = bv;
        __syncthreads();

#pragma unroll
        for (int k = 0; k < BK; k++) {
            float ar[TM], br[TN];
            *(float4*)&ar[0] = *(const float4*)&As[k][ty * TM];
            *(float4*)&ar[4] = *(const float4*)&As[k][ty * TM + 4];
            *(float4*)&br[0] = *(const float4*)&Bs[k][tx * TN];
            *(float4*)&br[4] = *(const float4*)&Bs[k][tx * TN + 4];
#pragma unroll
            for (int i = 0; i < TM; i++)
#pragma unroll
                for (int j = 0; j < TN; j++)
                    acc[i][j] = fmaf(ar[i], br[j], acc[i][j]);
        }
        __syncthreads();
    }

#pragma unroll
    for (int i = 0; i < TM; i++) {
        const size_t row = bm + ty * TM + i;
#pragma unroll
        for (int j = 0; j < TN; j += 4) {
            const int col = bn + tx * TN + j;
            float4 o;
            o.x = acc[i][j + 0] + bias[col + 0];
            o.y = acc[i][j + 1] + bias[col + 1];
            o.z = acc[i][j + 2] + bias[col + 2];
            o.w = acc[i][j + 3] + bias[col + 3];
            *(float4*)(C + row * N + col) = o;
        }
    }
}

// ---------------------------------------------------------------------------
// RoPE on q and k halves of g_qkv, in place. One thread per (t, h, d<40).
// ---------------------------------------------------------------------------
__global__ void rope_kernel(const float* __restrict__ rope)
{
    int idx = blockIdx.x * blockDim.x + threadIdx.x;
    const int HALF = HD / 2;  // 40
    if (idx >= TT * NH * HALF) return;
    const int d = idx % HALF;
    const int h = (idx / HALF) % NH;
    const int t = idx / (HALF * NH);

    const float ang = rope[t * HALF + d];
    float c, s;
    __sincosf(ang, &s, &c);
    // use accurate versions: recompute with sinf/cosf for safety
    c = cosf(ang); s = sinf(ang);

    float* q = g_qkv + (size_t)t * NQKV + h * HD;
    float xr = q[d], xi = q[d + HALF];
    q[d]        = xr * c - xi * s;
    q[d + HALF] = xr * s + xi * c;

    float* k = g_qkv + (size_t)t * NQKV + HIDN + h * HD;
    xr = k[d]; xi = k[d + HALF];
    k[d]        = xr * c - xi * s;
    k[d + HALF] = xr * s + xi * c;
}

// ---------------------------------------------------------------------------
// Windowed attention. One block per (window, head). Mask is exactly
// block-diagonal (windows are uniform 64 and T % 128 == 0 -> no padding,
// no intra-window masking). Dynamic smem: q/k/v tiles + score matrix.
// ---------------------------------------------------------------------------
#define HDP (HD + 1)   // 81: pad to kill bank conflicts on column access

__global__ __launch_bounds__(256)
void attn_kernel()
{
    extern __shared__ float smem[];
    float* qs = smem;                    // [WIN][HDP]
    float* ks = qs + WIN * HDP;          // [WIN][HDP]
    float* vs = ks + WIN * HDP;          // [WIN][HDP]
    float* sc = vs + WIN * HDP;          // [WIN][WIN]

    const int w = blockIdx.x;
    const int h = blockIdx.y;
    const int tid = threadIdx.x;
    const int t0 = w * WIN;

    // Load q, k, v tiles (64 x 80 each)
    for (int idx = tid; idx < WIN * HD; idx += 256) {
        const int r = idx / HD, c = idx % HD;
        const size_t base = (size_t)(t0 + r) * NQKV + h * HD + c;
        qs[r * HDP + c] = g_qkv[base];
        ks[r * HDP + c] = g_qkv[base + HIDN];
        vs[r * HDP + c] = g_qkv[base + 2 * HIDN];
    }
    __syncthreads();

    const float scale = rsqrtf((float)HD);

    // scores[i][j] = scale * dot(q_i, k_j); 4096 / 256 = 16 per thread
    for (int idx = tid; idx < WIN * WIN; idx += 256) {
        const int i = idx / WIN, j = idx % WIN;
        float s = 0.0f;
#pragma unroll
        for (int d = 0; d < HD; d++)
            s = fmaf(qs[i * HDP + d], ks[j * HDP + d], s);
        sc[i * WIN + j] = s * scale;
    }
    __syncthreads();

    // softmax per row: 4 threads per row (lanes are consecutive -> shfl ok)
    {
        const int row = tid / 4, l = tid % 4;
        float m = -1e30f;
        for (int j = l; j < WIN; j += 4) m = fmaxf(m, sc[row * WIN + j]);
        m = fmaxf(m, __shfl_xor_sync(0xffffffffu, m, 1));
        m = fmaxf(m, __shfl_xor_sync(0xffffffffu, m, 2));
        float ssum = 0.0f;
        for (int j = l; j < WIN; j += 4) {
            const float e = __expf(sc[row * WIN + j] - m);
            sc[row * WIN + j] = e;
            ssum += e;
        }
        ssum += __shfl_xor_sync(0xffffffffu, ssum, 1);
        ssum += __shfl_xor_sync(0xffffffffu, ssum, 2);
        const float inv = 1.0f / ssum;
        for (int j = l; j < WIN; j += 4) sc[row * WIN + j] *= inv;
    }
    __syncthreads();

    // out[i][d] = probs[i][:] @ v[:][d]; 5120 / 256 = 20 per thread
    for (int idx = tid; idx < WIN * HD; idx += 256) {
        const int i = idx / HD, d = idx % HD;
        float o = 0.0f;
#pragma unroll
        for (int j = 0; j < WIN; j++)
            o = fmaf(sc[i * WIN + j], vs[j * HDP + d], o);
        g_attn[(size_t)(t0 + i) * HIDN + h * HD + d] = o;
    }
}

// ---------------------------------------------------------------------------
// Launch
// ---------------------------------------------------------------------------
extern "C" void kernel_launch(void* const* d_in, const int* in_sizes, int n_in,
                              void* d_out, int out_size)
{
    const float* x    = (const float*)d_in[0];  // (2304,1,1280)
    const float* rope = (const float*)d_in[1];  // (2304,40)
    // d_in[2] = cu_window_seqlens: fixed uniform 64-token windows (hardcoded)
    const float* Wqkv = (const float*)d_in[3];  // (1280,3840)
    const float* bqkv = (const float*)d_in[4];  // (3840,)
    const float* Wo   = (const float*)d_in[5];  // (1280,1280)
    const float* bo   = (const float*)d_in[6];  // (1280,)
    float* out = (float*)d_out;                 // (2304,1,1280)

    float *qkv_ptr, *attn_ptr;
    cudaGetSymbolAddress((void**)&qkv_ptr,  g_qkv);
    cudaGetSymbolAddress((void**)&attn_ptr, g_attn);

    // Phase 1: QKV GEMM (2304 x 3840 x 1280)
    {
        dim3 grid(NQKV / 128, TT / 128);  // (30, 18)
        sgemm_bias_kernel<<<grid, 256>>>(x, Wqkv, bqkv, qkv_ptr, TT, NQKV, HIDN);
    }

    // Phase 2: RoPE (in place on q, k)
    {
        const int n = TT * NH * (HD / 2);
        rope_kernel<<<(n + 255) / 256, 256>>>(rope);
    }

    // Phase 3: windowed attention
    {
        const int smem_bytes = (3 * WIN * HDP + WIN * WIN) * (int)sizeof(float); // 78592
        static bool attr_set = false;
        // setting the attribute is idempotent; safe to repeat (not a stream op)
        cudaFuncSetAttribute(attn_kernel, cudaFuncAttributeMaxDynamicSharedMemorySize,
                             smem_bytes);
        (void)attr_set;
        dim3 grid(NWIN, NH);  // (36, 16)
        attn_kernel<<<grid, 256, smem_bytes>>>();
    }

    // Phase 4: output GEMM (2304 x 1280 x 1280)
    {
        dim3 grid(HIDN / 128, TT / 128);  // (10, 18)
        sgemm_bias_kernel<<<grid, 256>>>(attn_ptr, Wo, bo, out, TT, HIDN, HIDN);
    }
}

// round 3
// speedup vs baseline: 2.6760x; 2.6760x over previous
#include <cuda_runtime.h>
#include <math.h>
#include <stdint.h>

// ---------------------------------------------------------------------------
// Qwen2.5 Vision windowed attention.
//   GEMMs via mma.sync.m16n8k8 tf32 (sm_103 target lacks tcgen05 — PTX target
//   is non-'a', so arch-accelerated features are unavailable).
//   prep:  round x -> tf32; transpose+round Wqkv, Wo to [N][K]
//   GEMM1: qkv = x @ Wqkv + bqkv   (2304 x 3840 x 1280)
//   RoPE   (fp32, in place)
//   attn:  576 x (64x64x80) windowed blocks, fp32 SIMT, reg tiles
//   GEMM2: out = attn @ Wo + bo    (2304 x 1280 x 1280)
// ---------------------------------------------------------------------------

#define TT    2304
#define HIDN  1280
#define NH    16
#define HD    80
#define WIN   64
#define NWIN  (TT / WIN)      // 36
#define NQKV  (3 * HIDN)      // 3840

__device__ float g_qkv[TT * NQKV];
__device__ float g_attn[TT * HIDN];
__device__ float g_xr[TT * HIDN];
__device__ float g_WqkvT[NQKV * HIDN];
__device__ float g_WoT[HIDN * HIDN];

// ---------------------------------------------------------------------------
// helpers
// ---------------------------------------------------------------------------
__device__ __forceinline__ uint32_t smem_u32(const void* p) {
    uint32_t a;
    asm("{ .reg .u64 t; cvta.to.shared.u64 t, %1; cvt.u32.u64 %0, t; }"
        : "=r"(a) : "l"(p));
    return a;
}

__device__ __forceinline__ float tf32r(float x) {
    uint32_t r;
    asm("cvt.rna.tf32.f32 %0, %1;" : "=r"(r) : "f"(x));
    return __uint_as_float(r);
}

__device__ __forceinline__ void cpa16(uint32_t dst, const void* src) {
    asm volatile("cp.async.cg.shared.global [%0], [%1], 16;"
                 :: "r"(dst), "l"(src));
}

__device__ __forceinline__ void ldsm_x4(uint32_t (&r)[4], uint32_t addr) {
    asm volatile("ldmatrix.sync.aligned.m8n8.x4.shared.b16 {%0,%1,%2,%3}, [%4];"
                 : "=r"(r[0]), "=r"(r[1]), "=r"(r[2]), "=r"(r[3]) : "r"(addr));
}

__device__ __forceinline__ void ldsm_x2(uint32_t (&r)[2], uint32_t addr) {
    asm volatile("ldmatrix.sync.aligned.m8n8.x2.shared.b16 {%0,%1}, [%2];"
                 : "=r"(r[0]), "=r"(r[1]) : "r"(addr));
}

__device__ __forceinline__ void mma_tf32(float (&c)[4], const uint32_t (&a)[4],
                                         const uint32_t (&b)[2]) {
    asm volatile(
        "mma.sync.aligned.m16n8k8.row.col.f32.tf32.tf32.f32 "
        "{%0,%1,%2,%3}, {%4,%5,%6,%7}, {%8,%9}, {%0,%1,%2,%3};"
        : "+f"(c[0]), "+f"(c[1]), "+f"(c[2]), "+f"(c[3])
        : "r"(a[0]), "r"(a[1]), "r"(a[2]), "r"(a[3]), "r"(b[0]), "r"(b[1]));
}

// ---------------------------------------------------------------------------
// Prep kernels
// ---------------------------------------------------------------------------
__global__ void round_tf32_kernel(const float* __restrict__ in,
                                  float* __restrict__ out, int n) {
    int i = blockIdx.x * 256 + threadIdx.x;
    if (i < n) out[i] = tf32r(in[i]);
}

// W [K][N] -> Wt [N][K], tf32-rounded. block (32,8).
__global__ void transpose_round_kernel(const float* __restrict__ W,
                                       float* __restrict__ Wt, int K, int N) {
    __shared__ float t[32][33];
    const int n0 = blockIdx.x * 32, k0 = blockIdx.y * 32;
#pragma unroll
    for (int i = 0; i < 32; i += 8)
        t[threadIdx.y + i][threadIdx.x] =
            W[(size_t)(k0 + threadIdx.y + i) * N + n0 + threadIdx.x];
    __syncthreads();
#pragma unroll
    for (int i = 0; i < 32; i += 8)
        Wt[(size_t)(n0 + threadIdx.y + i) * K + k0 + threadIdx.x] =
            tf32r(t[threadIdx.x][threadIdx.y + i]);
}

// ---------------------------------------------------------------------------
// tf32 mma.sync GEMM: C[M,N] = A[M,K] @ Bt[N,K]^T + bias
//   CTA 128x128, 256 threads, warps 2(M) x 4(N), warp tile 64x32.
//   BK=32, 4-stage cp.async. Rows padded to 144B (36 words) so both
//   ldmatrix (8 rows, start banks 4r mod 32) and stores are conflict-free.
// ---------------------------------------------------------------------------
#define BM       128
#define BN       128
#define BK       32
#define STAGES   4
#define ROWB     144                      // bytes per padded smem row
#define ABYTES   (BM * ROWB)              // 18432
#define BBYTES   (BN * ROWB)              // 18432
#define ST_BYTES (ABYTES + BBYTES)        // 36864
#define GEMM_SMEM (STAGES * ST_BYTES)     // 147456

__device__ __forceinline__ void load_chunk(const float* __restrict__ A,
                                           const float* __restrict__ Bt,
                                           int K, int bm, int bn, int c,
                                           uint32_t stage_base, int tid) {
    const float* Ap = A  + (size_t)bm * K + c * BK;
    const float* Bp = Bt + (size_t)bn * K + c * BK;
#pragma unroll
    for (int i = 0; i < 4; i++) {            // A: 128 rows x 8 float4
        int u = tid + i * 256, r = u >> 3, g = u & 7;
        cpa16(stage_base + (uint32_t)(r * ROWB + g * 16),
              Ap + (size_t)r * K + g * 4);
    }
#pragma unroll
    for (int i = 0; i < 4; i++) {            // B: 128 rows x 8 float4
        int u = tid + i * 256, r = u >> 3, g = u & 7;
        cpa16(stage_base + ABYTES + (uint32_t)(r * ROWB + g * 16),
              Bp + (size_t)r * K + g * 4);
    }
}

__global__ __launch_bounds__(256, 1)
void tc_gemm_kernel(const float* __restrict__ A, const float* __restrict__ Bt,
                    const float* __restrict__ bias, float* __restrict__ C,
                    int N, int K)
{
    extern __shared__ char smraw[];
    const uint32_t sb = smem_u32(smraw);
    const int tid = threadIdx.x, wid = tid >> 5, lane = tid & 31;
    const int wm = wid & 1, wn = wid >> 1;          // warp grid 2 x 4
    const int gid = lane >> 2, tq = lane & 3;
    const int bm = blockIdx.y * BM, bn = blockIdx.x * BN;
    const int NC = K / BK;                          // 40

    // ldmatrix source addresses (stage 0, k0 = 0); add stage/k offsets later.
    // A x4: mat0=a0(row+0), mat1=a1(row+8), mat2=a2(col+16B), mat3=a3(row+8,col+16B)
    uint32_t addrA[4], addrB[4];
    {
        const int rIn = lane & 7, mIdx = lane >> 3;
#pragma unroll
        for (int mi = 0; mi < 4; mi++) {
            int row = wm * 64 + mi * 16 + (mIdx & 1) * 8 + rIn;
            addrA[mi] = sb + (uint32_t)(row * ROWB + (mIdx >> 1) * 16);
        }
#pragma unroll
        for (int ni = 0; ni < 4; ni++) {
            int row = wn * 32 + ni * 8 + rIn;                // n-rows of Bt
            addrB[ni] = sb + ABYTES + (uint32_t)(row * ROWB + ((mIdx & 1) * 16));
        }
    }

    float acc[4][4][4];
#pragma unroll
    for (int mi = 0; mi < 4; mi++)
#pragma unroll
        for (int ni = 0; ni < 4; ni++)
#pragma unroll
            for (int r = 0; r < 4; r++) acc[mi][ni][r] = 0.0f;

    // Prologue: chunks 0..2 -> stages 0..2
#pragma unroll
    for (int c = 0; c < STAGES - 1; c++) {
        load_chunk(A, Bt, K, bm, bn, c, sb + c * ST_BYTES, tid);
        asm volatile("cp.async.commit_group;" ::: "memory");
    }

    for (int c = 0; c < NC; c++) {
        const int s = c & (STAGES - 1);
        asm volatile("cp.async.wait_group %0;" :: "n"(STAGES - 2) : "memory");
        __syncthreads();

        const int cn = c + STAGES - 1;
        if (cn < NC)
            load_chunk(A, Bt, K, bm, bn, cn, sb + (cn & (STAGES - 1)) * ST_BYTES, tid);
        asm volatile("cp.async.commit_group;" ::: "memory");

        const uint32_t soff = (uint32_t)(s * ST_BYTES);
#pragma unroll
        for (int k0 = 0; k0 < BK; k0 += 8) {
            uint32_t af[4][4], bf[4][2];
#pragma unroll
            for (int mi = 0; mi < 4; mi++)
                ldsm_x4(af[mi], addrA[mi] + soff + k0 * 4);
#pragma unroll
            for (int ni = 0; ni < 4; ni++)
                ldsm_x2(bf[ni], addrB[ni] + soff + k0 * 4);
#pragma unroll
            for (int mi = 0; mi < 4; mi++)
#pragma unroll
                for (int ni = 0; ni < 4; ni++)
                    mma_tf32(acc[mi][ni], af[mi], bf[ni]);
        }
    }

    // Epilogue
#pragma unroll
    for (int mi = 0; mi < 4; mi++) {
        const int row = bm + wm * 64 + mi * 16 + gid;
#pragma unroll
        for (int ni = 0; ni < 4; ni++) {
            const int col = bn + wn * 32 + ni * 8 + tq * 2;
            const float bx = bias[col], by = bias[col + 1];
            float2 v0 = make_float2(acc[mi][ni][0] + bx, acc[mi][ni][1] + by);
            float2 v1 = make_float2(acc[mi][ni][2] + bx, acc[mi][ni][3] + by);
            *(float2*)(C + (size_t)row * N + col) = v0;
            *(float2*)(C + (size_t)(row + 8) * N + col) = v1;
        }
    }
}

// ---------------------------------------------------------------------------
// RoPE on q and k halves of g_qkv, in place.
// ---------------------------------------------------------------------------
__global__ void rope_kernel(const float* __restrict__ rope)
{
    int idx = blockIdx.x * blockDim.x + threadIdx.x;
    const int HALF = HD / 2;  // 40
    if (idx >= TT * NH * HALF) return;
    const int d = idx % HALF;
    const int h = (idx / HALF) % NH;
    const int t = idx / (HALF * NH);

    const float ang = rope[t * HALF + d];
    const float c = cosf(ang), s = sinf(ang);

    float* q = g_qkv + (size_t)t * NQKV + h * HD;
    float xr = q[d], xi = q[d + HALF];
    q[d]        = xr * c - xi * s;
    q[d + HALF] = xr * s + xi * c;

    float* k = g_qkv + (size_t)t * NQKV + HIDN + h * HD;
    xr = k[d]; xi = k[d + HALF];
    k[d]        = xr * c - xi * s;
    k[d + HALF] = xr * s + xi * c;
}

// ---------------------------------------------------------------------------
// Windowed attention, fp32 SIMT, 4x4 / 4x5 register tiles. Block-diagonal
// mask (uniform 64 windows, T % 128 == 0) -> no masking at all.
// Output rounded to tf32 for GEMM2.
// ---------------------------------------------------------------------------
#define HDP (HD + 1)   // 81

__global__ __launch_bounds__(256)
void attn_kernel()
{
    extern __shared__ float smem[];
    float* qs = smem;                    // [WIN][HDP]
    float* ks = qs + WIN * HDP;
    float* vs = ks + WIN * HDP;
    float* sc = vs + WIN * HDP;          // [WIN][WIN]

    const int w = blockIdx.x, h = blockIdx.y;
    const int tid = threadIdx.x;
    const int t0 = w * WIN;

    for (int idx = tid; idx < WIN * HD; idx += 256) {
        const int r = idx / HD, c = idx % HD;
        const size_t base = (size_t)(t0 + r) * NQKV + h * HD + c;
        qs[r * HDP + c] = g_qkv[base];
        ks[r * HDP + c] = g_qkv[base + HIDN];
        vs[r * HDP + c] = g_qkv[base + 2 * HIDN];
    }
    __syncthreads();

    const float scale = rsqrtf((float)HD);

    // scores: 4x4 tile per thread
    {
        const int ti = (tid >> 4) * 4, tj = (tid & 15) * 4;
        float acc[4][4] = {};
        for (int d = 0; d < HD; d++) {
            float qv[4], kv[4];
#pragma unroll
            for (int r = 0; r < 4; r++) qv[r] = qs[(ti + r) * HDP + d];
#pragma unroll
            for (int c = 0; c < 4; c++) kv[c] = ks[(tj + c) * HDP + d];
#pragma unroll
            for (int r = 0; r < 4; r++)
#pragma unroll
                for (int c = 0; c < 4; c++)
                    acc[r][c] = fmaf(qv[r], kv[c], acc[r][c]);
        }
#pragma unroll
        for (int r = 0; r < 4; r++)
#pragma unroll
            for (int c = 0; c < 4; c++)
                sc[(ti + r) * WIN + tj + c] = acc[r][c] * scale;
    }
    __syncthreads();

    // softmax per row: 4 threads per row
    {
        const int row = tid / 4, l = tid % 4;
        float m = -1e30f;
        for (int j = l; j < WIN; j += 4) m = fmaxf(m, sc[row * WIN + j]);
        m = fmaxf(m, __shfl_xor_sync(0xffffffffu, m, 1));
        m = fmaxf(m, __shfl_xor_sync(0xffffffffu, m, 2));
        float ssum = 0.0f;
        for (int j = l; j < WIN; j += 4) {
            const float e = __expf(sc[row * WIN + j] - m);
            sc[row * WIN + j] = e;
            ssum += e;
        }
        ssum += __shfl_xor_sync(0xffffffffu, ssum, 1);
        ssum += __shfl_xor_sync(0xffffffffu, ssum, 2);
        const float inv = 1.0f / ssum;
        for (int j = l; j < WIN; j += 4) sc[row * WIN + j] *= inv;
    }
    __syncthreads();

    // PV: 4(row) x 5(dim) tile per thread
    {
        const int oi = (tid >> 4) * 4, od = (tid & 15) * 5;
        float acc[4][5] = {};
        for (int j = 0; j < WIN; j++) {
            float pv[4], vv[5];
#pragma unroll
            for (int r = 0; r < 4; r++) pv[r] = sc[(oi + r) * WIN + j];
#pragma unroll
            for (int c = 0; c < 5; c++) vv[c] = vs[j * HDP + od + c];
#pragma unroll
            for (int r = 0; r < 4; r++)
#pragma unroll
                for (int c = 0; c < 5; c++)
                    acc[r][c] = fmaf(pv[r], vv[c], acc[r][c]);
        }
#pragma unroll
        for (int r = 0; r < 4; r++)
#pragma unroll
            for (int c = 0; c < 5; c++)
                g_attn[(size_t)(t0 + oi + r) * HIDN + h * HD + od + c] =
                    tf32r(acc[r][c]);
    }
}

// ---------------------------------------------------------------------------
// Launch
// ---------------------------------------------------------------------------
extern "C" void kernel_launch(void* const* d_in, const int* in_sizes, int n_in,
                              void* d_out, int out_size)
{
    const float* x    = (const float*)d_in[0];
    const float* rope = (const float*)d_in[1];
    // d_in[2] = cu_window_seqlens (fixed uniform 64-token windows; hardcoded)
    const float* Wqkv = (const float*)d_in[3];
    const float* bqkv = (const float*)d_in[4];
    const float* Wo   = (const float*)d_in[5];
    const float* bo   = (const float*)d_in[6];
    float* out = (float*)d_out;

    float *qkv_p, *attn_p, *xr_p, *wqt_p, *wot_p;
    cudaGetSymbolAddress((void**)&qkv_p,  g_qkv);
    cudaGetSymbolAddress((void**)&attn_p, g_attn);
    cudaGetSymbolAddress((void**)&xr_p,   g_xr);
    cudaGetSymbolAddress((void**)&wqt_p,  g_WqkvT);
    cudaGetSymbolAddress((void**)&wot_p,  g_WoT);

    cudaFuncSetAttribute(tc_gemm_kernel,
                         cudaFuncAttributeMaxDynamicSharedMemorySize, GEMM_SMEM);
    const int attn_smem = (3 * WIN * HDP + WIN * WIN) * (int)sizeof(float);
    cudaFuncSetAttribute(attn_kernel,
                         cudaFuncAttributeMaxDynamicSharedMemorySize, attn_smem);

    // Prep
    {
        const int n = TT * HIDN;
        round_tf32_kernel<<<(n + 255) / 256, 256>>>(x, xr_p, n);
        dim3 blk(32, 8);
        transpose_round_kernel<<<dim3(NQKV / 32, HIDN / 32), blk>>>(Wqkv, wqt_p, HIDN, NQKV);
        transpose_round_kernel<<<dim3(HIDN / 32, HIDN / 32), blk>>>(Wo,   wot_p, HIDN, HIDN);
    }

    // GEMM1: qkv = x @ Wqkv + bqkv
    tc_gemm_kernel<<<dim3(NQKV / BN, TT / BM), 256, GEMM_SMEM>>>(
        xr_p, wqt_p, bqkv, qkv_p, NQKV, HIDN);

    // RoPE
    {
        const int n = TT * NH * (HD / 2);
        rope_kernel<<<(n + 255) / 256, 256>>>(rope);
    }

    // Attention
    attn_kernel<<<dim3(NWIN, NH), 256, attn_smem>>>();

    // GEMM2: out = attn @ Wo + bo
    tc_gemm_kernel<<<dim3(HIDN / BN, TT / BM), 256, GEMM_SMEM>>>(
        attn_p, wot_p, bo, out, HIDN, HIDN);
}